// round 16
// baseline (speedup 1.0000x reference)
#include <cuda_runtime.h>
#include <cuda_bf16.h>
#include <cstdint>
#include <math.h>

#define N_NODES 50000
#define ROWS_PAD 50048       /* 391*128 */
#define RB_CNT  391
#define N_EDGES 400000
#define E_TOT   450000
#define IN_CH   814
#define KP1     832          /* 13*64 */
#define NCK1    13
#define HID     128
#define HEADS1  4
#define D1      (HEADS1*HID) /* 512 */
#define NCK2    8
#define NUM_CLASSES 46
#define NUM_GRAPHS  64
#define NEG_SLOPE   0.2f
#define SCAN_NB  196

#if defined(__CUDA_ARCH_FEAT_SM103_ALL) || defined(__CUDA_ARCH_FEAT_SM100_ALL)
#define HAS_TC 1
#else
#define HAS_TC 0
#endif

// ---------------- scratch (tiled operands: 16KB SW128 tiles, chunk-contiguous) ----
__device__ float g_h1[N_NODES * D1];
__device__ float g_h2[N_NODES * HID];
__device__ __nv_bfloat16 g_xh[ROWS_PAD * KP1];
__device__ __nv_bfloat16 g_xl[ROWS_PAD * KP1];
__device__ __nv_bfloat16 g_o1h[ROWS_PAD * D1];
__device__ __nv_bfloat16 g_o1l[ROWS_PAD * D1];
__device__ __nv_bfloat16 g_b1h[D1 * KP1];
__device__ __nv_bfloat16 g_b1l[D1 * KP1];
__device__ __nv_bfloat16 g_b2h[HID * D1];
__device__ __nv_bfloat16 g_b2l[HID * D1];
__device__ float g_als1[N_NODES * HEADS1];
__device__ float g_ald1[N_NODES * HEADS1];
__device__ float g_als2[N_NODES];
__device__ float g_ald2[N_NODES];
__device__ int   g_counts[N_NODES];
__device__ int   g_offsets[N_NODES + 1];
__device__ int   g_cursor[N_NODES];
__device__ int   g_bsum[SCAN_NB];
__device__ int   g_src_sorted[E_TOT];
__device__ float g_alpha1[E_TOT * HEADS1];
__device__ float g_alpha2[E_TOT];
__device__ float g_pool[NUM_GRAPHS * HID];
__device__ int   g_cnt[NUM_GRAPHS];

// tiled byte-offset: tile = (row>>7)*nck + (k>>6); within: SW128 of (row&127)*128+(k&63)*2
__device__ __forceinline__ size_t tidx(int row, int k, int nck) {
    uint32_t byte = ((uint32_t)(row & 127)) * 128u + (uint32_t)(k & 63) * 2u;
    byte ^= (byte >> 3) & 0x70u;
    return ((size_t)((row >> 7) * nck + (k >> 6)) << 14) + byte;
}

// ---------------- PTX helpers ----------------------------------------------------
#if HAS_TC
__device__ __forceinline__ uint32_t smem_u32(const void* p) {
    uint32_t a;
    asm("{ .reg .u64 t; cvta.to.shared.u64 t, %1; cvt.u32.u64 %0, t; }" : "=r"(a) : "l"(p));
    return a;
}
__device__ __forceinline__ uint32_t elect_one() {
    uint32_t pred;
    asm volatile("{ .reg .pred p; elect.sync _|p, 0xFFFFFFFF; selp.b32 %0, 1, 0, p; }" : "=r"(pred));
    return pred;
}
#define MBAR_INIT(a, n)  asm volatile("mbarrier.init.shared.b64 [%0], %1;" :: "r"(a), "r"((uint32_t)(n)) : "memory")
#define MBAR_EXPECT(a, b) asm volatile("mbarrier.arrive.expect_tx.shared.b64 _, [%0], %1;" :: "r"(a), "r"((uint32_t)(b)) : "memory")
#define MBAR_WAIT(a, ph) do { \
    uint32_t _m = (a), _p = (ph), _d; \
    asm volatile("{ .reg .pred p; mbarrier.try_wait.parity.acquire.cta.shared::cta.b64 p, [%1], %2; selp.b32 %0,1,0,p; }" \
        : "=r"(_d) : "r"(_m), "r"(_p) : "memory"); \
    if (!_d) { \
        asm volatile("{ .reg .pred P1;\nWL_%=:\nmbarrier.try_wait.parity.acquire.cta.shared::cta.b64 P1, [%0], %1, 0x989680;\n@P1 bra.uni WD_%=;\nbra.uni WL_%=;\nWD_%=:\n}" \
            :: "r"(_m), "r"(_p) : "memory"); \
    } } while (0)
#define TC_ALLOC(sa, n)   asm volatile("tcgen05.alloc.cta_group::1.sync.aligned.shared::cta.b32 [%0], %1;" :: "r"(sa), "r"((uint32_t)(n)) : "memory")
#define TC_DEALLOC(t, n)  asm volatile("tcgen05.dealloc.cta_group::1.sync.aligned.b32 %0, %1;" :: "r"(t), "r"((uint32_t)(n)))
#define TC_RELINQ()       asm volatile("tcgen05.relinquish_alloc_permit.cta_group::1.sync.aligned;")
#define TC_COMMIT(a)      asm volatile("tcgen05.commit.cta_group::1.mbarrier::arrive::one.shared::cluster.b64 [%0];" :: "r"(a) : "memory")
#define TC_FENCE_AFTER()  asm volatile("tcgen05.fence::after_thread_sync;" ::: "memory")
#define TC_FENCE_BEFORE() asm volatile("tcgen05.fence::before_thread_sync;" ::: "memory")
#define TC_WAIT_LD()      asm volatile("tcgen05.wait::ld.sync.aligned;" ::: "memory")
#define BULK_CP(dst, src, sz, mbar) \
    asm volatile("cp.async.bulk.shared::cta.global.mbarrier::complete_tx::bytes [%0], [%1], %2, [%3];" \
                 :: "r"(dst), "l"(src), "r"((uint32_t)(sz)), "r"(mbar) : "memory")
#define PREF_L2(src, sz) \
    asm volatile("cp.async.bulk.prefetch.L2.global [%0], %1;" :: "l"(src), "r"((uint32_t)(sz)) : "memory")

__device__ __forceinline__ void mma_f16_ss(uint32_t d, uint64_t ad, uint64_t bd,
                                           uint32_t idesc, bool accum) {
    uint32_t en = accum ? 1u : 0u, z = 0u;
    asm volatile(
        "{ .reg .pred p; setp.ne.u32 p, %5, 0;\n\t"
        "tcgen05.mma.cta_group::1.kind::f16 [%0], %1, %2, %3, {%4,%4,%4,%4}, p; }"
        :: "r"(d), "l"(ad), "l"(bd), "r"(idesc), "r"(z), "r"(en) : "memory");
}
__device__ __forceinline__ void tmem_ld32(uint32_t* r, uint32_t addr) {
    asm volatile(
        "tcgen05.ld.sync.aligned.32x32b.x32.b32 "
        "{%0,%1,%2,%3,%4,%5,%6,%7,%8,%9,%10,%11,%12,%13,%14,%15,"
        "%16,%17,%18,%19,%20,%21,%22,%23,%24,%25,%26,%27,%28,%29,%30,%31}, [%32];"
        : "=r"(r[0]), "=r"(r[1]), "=r"(r[2]), "=r"(r[3]), "=r"(r[4]), "=r"(r[5]), "=r"(r[6]), "=r"(r[7]),
          "=r"(r[8]), "=r"(r[9]), "=r"(r[10]), "=r"(r[11]), "=r"(r[12]), "=r"(r[13]), "=r"(r[14]), "=r"(r[15]),
          "=r"(r[16]), "=r"(r[17]), "=r"(r[18]), "=r"(r[19]), "=r"(r[20]), "=r"(r[21]), "=r"(r[22]), "=r"(r[23]),
          "=r"(r[24]), "=r"(r[25]), "=r"(r[26]), "=r"(r[27]), "=r"(r[28]), "=r"(r[29]), "=r"(r[30]), "=r"(r[31])
        : "r"(addr));
}
#define DESC_SW128(addr) ((uint64_t(2) << 61) | (uint64_t(1) << 46) | (uint64_t(64) << 32) \
                          | (uint64_t(1) << 16) | ((uint64_t)((addr) >> 4) & 0x3FFF))
#endif // HAS_TC

// -------- tcgen05 bf16x3 GEMM, software-pipelined; single elected pipeline thread ---
// Parity safety: ONLY the elected thread waits the MMA barriers (it visits every
// phase of each barrier in order); all other threads are released by __syncthreads().
template <int NT>
__global__ void __launch_bounds__(256)
gemm_tc(const __nv_bfloat16* __restrict__ Ah, const __nv_bfloat16* __restrict__ Al,
        const __nv_bfloat16* __restrict__ Bh, const __nv_bfloat16* __restrict__ Bl,
        float* __restrict__ C, int M, int ldc, int kp,
        const float* __restrict__ asrc, const float* __restrict__ adst,
        float* __restrict__ als, float* __restrict__ ald, int nheads)
{
#if HAS_TC
    extern __shared__ char dsm[];
    uint32_t sb = smem_u32(dsm);
    uint32_t base = (sb + 1023) & ~1023u;
    const uint32_t TM_PTR = base;
    const uint32_t MMAB0  = base + 8;    // MMA completion, even chunks
    const uint32_t MMAB1  = base + 16;   // MMA completion, odd chunks
    const uint32_t LBAR0  = base + 24;
    const uint32_t LBAR1  = base + 32;
    const uint32_t T0 = base + 1024;
    constexpr uint32_t ATILE = 16384;
    constexpr uint32_t BTILE = NT * 128;
    constexpr uint32_t OFF_AL = ATILE;
    constexpr uint32_t OFF_BH = 2 * ATILE;
    constexpr uint32_t OFF_BL = 2 * ATILE + BTILE;
    constexpr uint32_t BUFSZ  = 2 * ATILE + 2 * BTILE;
    constexpr uint32_t LOADB  = BUFSZ;

    int tid = threadIdx.x, wid = tid >> 5, lane = tid & 31;
    int rb = blockIdx.y;
    int m0 = rb * 128, n0 = blockIdx.x * NT;
    int nb0 = n0 >> 7;
    const int nck = kp >> 6;

    if (wid == 0) { TC_ALLOC(TM_PTR, NT); TC_RELINQ(); }
    if (tid == 0) {
        MBAR_INIT(MMAB0, 1);
        MBAR_INIT(MMAB1, 1);
        MBAR_INIT(LBAR0, 1);
        MBAR_INIT(LBAR1, 1);
    }
    __syncthreads();
    uint32_t tmem;
    asm volatile("ld.shared.b32 %0, [%1];" : "=r"(tmem) : "r"(TM_PTR));

    const char* cAh = (const char*)Ah;
    const char* cAl = (const char*)Al;
    const char* cBh = (const char*)Bh;
    const char* cBl = (const char*)Bl;

    const uint32_t IDESC = 0x8000490u | ((NT / 8) << 17);

    auto issue = [&](int c, uint32_t buf, uint32_t lbar) {
        MBAR_EXPECT(lbar, LOADB);
        size_t aoff = ((size_t)(rb * nck + c)) << 14;
        BULK_CP(buf,          cAh + aoff, 16384, lbar);
        BULK_CP(buf + OFF_AL, cAl + aoff, 16384, lbar);
        size_t b0off = ((size_t)(nb0 * nck + c)) << 14;
        BULK_CP(buf + OFF_BH, cBh + b0off, 16384, lbar);
        BULK_CP(buf + OFF_BL, cBl + b0off, 16384, lbar);
        if (NT == 256) {
            size_t b1off = ((size_t)((nb0 + 1) * nck + c)) << 14;
            BULK_CP(buf + OFF_BH + 16384, cBh + b1off, 16384, lbar);
            BULK_CP(buf + OFF_BL + 16384, cBl + b1off, 16384, lbar);
        }
    };
    auto pref = [&](int c) {
        size_t aoff = ((size_t)(rb * nck + c)) << 14;
        PREF_L2(cAh + aoff, 16384);
        PREF_L2(cAl + aoff, 16384);
        size_t b0off = ((size_t)(nb0 * nck + c)) << 14;
        PREF_L2(cBh + b0off, 16384);
        PREF_L2(cBl + b0off, 16384);
        if (NT == 256) {
            size_t b1off = ((size_t)((nb0 + 1) * nck + c)) << 14;
            PREF_L2(cBh + b1off, 16384);
            PREF_L2(cBl + b1off, 16384);
        }
    };

    // Entire pipeline (loads, MMAs, waits) driven by ONE elected thread of warp 0.
    // Its parity waits on each barrier are strictly sequential (no phase aliasing).
    if (wid == 0 && elect_one()) {
        issue(0, T0, LBAR0);
        if (1 < nck) pref(1);
        if (2 < nck) pref(2);
        if (3 < nck) pref(3);
        for (int c = 0; c < nck; c++) {
            uint32_t buf = T0 + (c & 1) * BUFSZ;
            MBAR_WAIT((c & 1) ? LBAR1 : LBAR0, (c >> 1) & 1);
            uint64_t dAH = DESC_SW128(buf);
            uint64_t dAL = DESC_SW128(buf + OFF_AL);
            uint64_t dBH = DESC_SW128(buf + OFF_BH);
            uint64_t dBL = DESC_SW128(buf + OFF_BL);
#pragma unroll
            for (int k = 0; k < 4; k++) mma_f16_ss(tmem, dAH + 2 * k, dBH + 2 * k, IDESC, !(c == 0 && k == 0));
#pragma unroll
            for (int k = 0; k < 4; k++) mma_f16_ss(tmem, dAL + 2 * k, dBH + 2 * k, IDESC, true);
#pragma unroll
            for (int k = 0; k < 4; k++) mma_f16_ss(tmem, dAH + 2 * k, dBL + 2 * k, IDESC, true);
            TC_COMMIT((c & 1) ? MMAB1 : MMAB0);
            if (c + 1 < nck) {
                // buffer (c+1)&1 was last read by MMA(c-1): wait that, not MMA(c)
                if (c >= 1)
                    MBAR_WAIT(((c - 1) & 1) ? MMAB1 : MMAB0, ((c - 1) >> 1) & 1);
                issue(c + 1, T0 + ((c + 1) & 1) * BUFSZ, ((c + 1) & 1) ? LBAR1 : LBAR0);
                if (c + 4 < nck) pref(c + 4);
            }
        }
        // final: wait last chunk's MMA (sequential next phase for this thread)
        int lc = nck - 1;
        MBAR_WAIT((lc & 1) ? MMAB1 : MMAB0, (lc >> 1) & 1);
    }
    // release all other threads only after the elected thread confirmed completion
    __syncthreads();

    TC_FENCE_AFTER();
    if (wid < 4) {
        int row = m0 + wid * 32 + lane;
#pragma unroll
        for (int hloc = 0; hloc < NT / 128; hloc++) {
            float s = 0.f, d = 0.f;
#pragma unroll
            for (int nb = 0; nb < 4; nb++) {
                int batch = hloc * 4 + nb;
                uint32_t rg[32];
                tmem_ld32(rg, tmem + batch * 32);
                TC_WAIT_LD();
                if (row < M) {
                    float4* dst = (float4*)(C + (size_t)row * ldc + n0 + batch * 32);
#pragma unroll
                    for (int i = 0; i < 8; i++)
                        dst[i] = make_float4(__uint_as_float(rg[4 * i]), __uint_as_float(rg[4 * i + 1]),
                                             __uint_as_float(rg[4 * i + 2]), __uint_as_float(rg[4 * i + 3]));
                }
#pragma unroll
                for (int i = 0; i < 32; i++) {
                    float v = __uint_as_float(rg[i]);
                    int col = n0 + batch * 32 + i;
                    s = fmaf(v, __ldg(&asrc[col]), s);
                    d = fmaf(v, __ldg(&adst[col]), d);
                }
            }
            if (row < M) {
                int head = n0 / 128 + hloc;
                als[(size_t)row * nheads + head] = s;
                ald[(size_t)row * nheads + head] = d;
            }
        }
        TC_FENCE_BEFORE();
    }
    __syncthreads();
    if (wid == 0) TC_DEALLOC(tmem, NT);
#endif
}

// ---------------- SIMT fallback (active only when !HAS_TC; reads tiled layout) -----
__global__ __launch_bounds__(256) void gemm_simt(
    const __nv_bfloat16* __restrict__ Ah, const __nv_bfloat16* __restrict__ Al,
    const __nv_bfloat16* __restrict__ Bh, const __nv_bfloat16* __restrict__ Bl,
    float* __restrict__ C, int M, int ldc, int kp)
{
#if !HAS_TC
    __shared__ float As[8][128];
    __shared__ float Bs[8][128];
    int tid = threadIdx.x;
    int tx = tid & 15, ty = tid >> 4;
    int rowBase = blockIdx.y * 128;
    int colBase = blockIdx.x * 128;
    int nck = kp >> 6;

    float acc[8][8];
#pragma unroll
    for (int i = 0; i < 8; i++)
#pragma unroll
        for (int j = 0; j < 8; j++) acc[i][j] = 0.f;

    for (int k0 = 0; k0 < kp; k0 += 8) {
#pragma unroll
        for (int i = 0; i < 4; i++) {
            int idx = tid + 256 * i;
            int rr = idx >> 3, cc = idx & 7;
            int gr = rowBase + rr;
            size_t o = tidx(gr, k0 + cc, nck);
            float v = __bfloat162float(*(const __nv_bfloat16*)((const char*)Ah + o))
                    + __bfloat162float(*(const __nv_bfloat16*)((const char*)Al + o));
            As[cc][rr] = v;
        }
#pragma unroll
        for (int i = 0; i < 4; i++) {
            int idx = tid + 256 * i;
            int nl = idx >> 3, kk = idx & 7;
            size_t o = tidx(colBase + nl, k0 + kk, nck);
            Bs[kk][nl] = __bfloat162float(*(const __nv_bfloat16*)((const char*)Bh + o))
                       + __bfloat162float(*(const __nv_bfloat16*)((const char*)Bl + o));
        }
        __syncthreads();
#pragma unroll
        for (int kk = 0; kk < 8; kk++) {
            float a[8], b[8];
#pragma unroll
            for (int i = 0; i < 8; i++) a[i] = As[kk][ty * 8 + i];
#pragma unroll
            for (int j = 0; j < 8; j++) b[j] = Bs[kk][tx * 8 + j];
#pragma unroll
            for (int i = 0; i < 8; i++)
#pragma unroll
                for (int j = 0; j < 8; j++) acc[i][j] = fmaf(a[i], b[j], acc[i][j]);
        }
        __syncthreads();
    }
#pragma unroll
    for (int i = 0; i < 8; i++) {
        int gr = rowBase + ty * 8 + i;
        if (gr >= M) continue;
#pragma unroll
        for (int j = 0; j < 8; j++)
            C[(size_t)gr * ldc + colBase + tx * 8 + j] = acc[i][j];
    }
#endif
}

// ---------------- misc helpers -----------------------------------------------
__device__ __forceinline__ float warpMax(float v) {
#pragma unroll
    for (int o = 16; o > 0; o >>= 1) v = fmaxf(v, __shfl_xor_sync(0xffffffffu, v, o));
    return v;
}
__device__ __forceinline__ float warpSum(float v) {
#pragma unroll
    for (int o = 16; o > 0; o >>= 1) v += __shfl_xor_sync(0xffffffffu, v, o);
    return v;
}
__device__ __forceinline__ float lrelu(float x) { return x > 0.f ? x : NEG_SLOPE * x; }
__device__ __forceinline__ uint32_t packbf2(float a, float b) {
    __nv_bfloat162 t;
    t.x = __float2bfloat16(a);
    t.y = __float2bfloat16(b);
    return *(uint32_t*)&t;
}

// ---------------- conversions (vectorized: 8 elems -> one uint4 per table) -------
__global__ void cvt_x_kernel(const float* __restrict__ x) {
    int idx = blockIdx.x * blockDim.x + threadIdx.x;
    const int GPR = KP1 / 8;
    if (idx >= ROWS_PAD * GPR) return;
    int row = idx / GPR, k0 = (idx - row * GPR) * 8;
    float f[8];
#pragma unroll
    for (int j = 0; j < 8; j++) {
        int k = k0 + j;
        f[j] = (row < N_NODES && k < IN_CH) ? __ldg(&x[(size_t)row * IN_CH + k]) : 0.f;
    }
    uint4 hiw, low;
    uint32_t* hp = (uint32_t*)&hiw;
    uint32_t* lp = (uint32_t*)&low;
#pragma unroll
    for (int j = 0; j < 4; j++) {
        float h0 = __bfloat162float(__float2bfloat16(f[2 * j]));
        float h1 = __bfloat162float(__float2bfloat16(f[2 * j + 1]));
        hp[j] = packbf2(f[2 * j], f[2 * j + 1]);
        lp[j] = packbf2(f[2 * j] - h0, f[2 * j + 1] - h1);
    }
    size_t o = tidx(row, k0, NCK1);
    *(uint4*)((char*)g_xh + o) = hiw;
    *(uint4*)((char*)g_xl + o) = low;
}

__global__ void cvt_w_kernel(const float* __restrict__ W1, const float* __restrict__ W2) {
    int idx = blockIdx.x * blockDim.x + threadIdx.x;
    const int G1 = D1 * (KP1 / 8);
    if (idx < G1) {
        int n = idx / (KP1 / 8), k0 = (idx - n * (KP1 / 8)) * 8;
        float f[8];
#pragma unroll
        for (int j = 0; j < 8; j++) {
            int k = k0 + j;
            f[j] = (k < IN_CH) ? __ldg(&W1[(size_t)k * D1 + n]) : 0.f;
        }
        uint4 hiw, low;
        uint32_t* hp = (uint32_t*)&hiw;
        uint32_t* lp = (uint32_t*)&low;
#pragma unroll
        for (int j = 0; j < 4; j++) {
            float h0 = __bfloat162float(__float2bfloat16(f[2 * j]));
            float h1 = __bfloat162float(__float2bfloat16(f[2 * j + 1]));
            hp[j] = packbf2(f[2 * j], f[2 * j + 1]);
            lp[j] = packbf2(f[2 * j] - h0, f[2 * j + 1] - h1);
        }
        size_t o = tidx(n, k0, NCK1);
        *(uint4*)((char*)g_b1h + o) = hiw;
        *(uint4*)((char*)g_b1l + o) = low;
        return;
    }
    int j2 = idx - G1;
    const int G2 = HID * (D1 / 8);
    if (j2 < G2) {
        int n = j2 / (D1 / 8), k0 = (j2 - n * (D1 / 8)) * 8;
        float f[8];
#pragma unroll
        for (int j = 0; j < 8; j++)
            f[j] = __ldg(&W2[(size_t)(k0 + j) * HID + n]);
        uint4 hiw, low;
        uint32_t* hp = (uint32_t*)&hiw;
        uint32_t* lp = (uint32_t*)&low;
#pragma unroll
        for (int j = 0; j < 4; j++) {
            float h0 = __bfloat162float(__float2bfloat16(f[2 * j]));
            float h1 = __bfloat162float(__float2bfloat16(f[2 * j + 1]));
            hp[j] = packbf2(f[2 * j], f[2 * j + 1]);
            lp[j] = packbf2(f[2 * j] - h0, f[2 * j + 1] - h1);
        }
        size_t o = tidx(n, k0, NCK2);
        *(uint4*)((char*)g_b2h + o) = hiw;
        *(uint4*)((char*)g_b2l + o) = low;
    }
}

__global__ void zero_kernel() {
    int i = blockIdx.x * blockDim.x + threadIdx.x;
    if (i < N_NODES) g_counts[i] = 0;
    if (i < NUM_GRAPHS * HID) g_pool[i] = 0.f;
    if (i < NUM_GRAPHS) g_cnt[i] = 0;
}

__global__ void hist_kernel(const int* __restrict__ ei) {
    int e = blockIdx.x * blockDim.x + threadIdx.x;
    if (e >= E_TOT) return;
    int dst = (e < N_EDGES) ? ei[N_EDGES + e] : (e - N_EDGES);
    atomicAdd(&g_counts[dst], 1);
}

__global__ void scan1_kernel() {
    __shared__ int sh[256];
    int b = blockIdx.x, tid = threadIdx.x;
    int i = b * 256 + tid;
    int v = (i < N_NODES) ? g_counts[i] : 0;
    sh[tid] = v;
    __syncthreads();
#pragma unroll
    for (int o = 1; o < 256; o <<= 1) {
        int t = (tid >= o) ? sh[tid - o] : 0;
        __syncthreads();
        sh[tid] += t;
        __syncthreads();
    }
    if (i < N_NODES) g_offsets[i] = sh[tid] - v;
    if (tid == 255) g_bsum[b] = sh[255];
}

__global__ void scan2_kernel() {
    __shared__ int sh[SCAN_NB];
    int tid = threadIdx.x;
    int v = (tid < SCAN_NB) ? g_bsum[tid] : 0;
    if (tid < SCAN_NB) sh[tid] = v;
    __syncthreads();
    for (int o = 1; o < SCAN_NB; o <<= 1) {
        int t = (tid >= o && tid < SCAN_NB) ? sh[tid - o] : 0;
        __syncthreads();
        if (tid < SCAN_NB) sh[tid] += t;
        __syncthreads();
    }
    if (tid < SCAN_NB) g_bsum[tid] = sh[tid] - v;
    if (tid == 0) g_offsets[N_NODES] = E_TOT;
}

__global__ void scan3_kernel() {
    int b = blockIdx.x, tid = threadIdx.x;
    int i = b * 256 + tid;
    if (i >= N_NODES) return;
    int off = g_offsets[i] + g_bsum[b];
    g_offsets[i] = off;
    g_cursor[i] = off;
}

__global__ void scatter_kernel(const int* __restrict__ ei) {
    int e = blockIdx.x * blockDim.x + threadIdx.x;
    if (e >= E_TOT) return;
    int src, dst;
    if (e < N_EDGES) { src = ei[e]; dst = ei[N_EDGES + e]; }
    else             { src = e - N_EDGES; dst = src; }
    int pos = atomicAdd(&g_cursor[dst], 1);
    g_src_sorted[pos] = src;
}

// ---------------- attention coefficients (fallback only) ---------------------------
__global__ void att_coef1(const float* __restrict__ a_src, const float* __restrict__ a_dst) {
#if !HAS_TC
    int gw = (blockIdx.x * blockDim.x + threadIdx.x) >> 5;
    int lane = threadIdx.x & 31;
    if (gw >= N_NODES) return;
    const float* row = g_h1 + (size_t)gw * D1;
    float s[4] = {0, 0, 0, 0}, d[4] = {0, 0, 0, 0};
#pragma unroll
    for (int j = 0; j < 16; j++) {
        int c = lane + 32 * j;
        float v = row[c];
        s[j >> 2] = fmaf(v, a_src[c], s[j >> 2]);
        d[j >> 2] = fmaf(v, a_dst[c], d[j >> 2]);
    }
#pragma unroll
    for (int h = 0; h < 4; h++) { s[h] = warpSum(s[h]); d[h] = warpSum(d[h]); }
    if (lane == 0) {
#pragma unroll
        for (int h = 0; h < 4; h++) {
            g_als1[gw * 4 + h] = s[h];
            g_ald1[gw * 4 + h] = d[h];
        }
    }
#endif
}

__global__ void att_coef2(const float* __restrict__ a_src, const float* __restrict__ a_dst) {
#if !HAS_TC
    int gw = (blockIdx.x * blockDim.x + threadIdx.x) >> 5;
    int lane = threadIdx.x & 31;
    if (gw >= N_NODES) return;
    const float* row = g_h2 + (size_t)gw * HID;
    float s = 0.f, d = 0.f;
#pragma unroll
    for (int j = 0; j < 4; j++) {
        int c = lane + 32 * j;
        float v = row[c];
        s = fmaf(v, a_src[c], s);
        d = fmaf(v, a_dst[c], d);
    }
    s = warpSum(s); d = warpSum(d);
    if (lane == 0) { g_als2[gw] = s; g_ald2[gw] = d; }
#endif
}

// ---------------- GAT layer 1 softmax + aggregate (warp per dst node) ------------
__global__ __launch_bounds__(256) void gat_agg1(const float* __restrict__ b1) {
    int gw = (blockIdx.x * blockDim.x + threadIdx.x) >> 5;
    int lane = threadIdx.x & 31;
    if (gw >= N_NODES) return;
    int beg = g_offsets[gw], end = g_offsets[gw + 1];

    float ald[4];
#pragma unroll
    for (int h = 0; h < 4; h++) ald[h] = g_ald1[gw * 4 + h];

    float mx[4] = {-1e30f, -1e30f, -1e30f, -1e30f};
    for (int i = beg + lane; i < end; i += 32) {
        int s = g_src_sorted[i];
        float4 al = ((const float4*)g_als1)[s];
        mx[0] = fmaxf(mx[0], lrelu(al.x + ald[0]));
        mx[1] = fmaxf(mx[1], lrelu(al.y + ald[1]));
        mx[2] = fmaxf(mx[2], lrelu(al.z + ald[2]));
        mx[3] = fmaxf(mx[3], lrelu(al.w + ald[3]));
    }
#pragma unroll
    for (int h = 0; h < 4; h++) mx[h] = warpMax(mx[h]);

    float sm[4] = {0, 0, 0, 0};
    for (int i = beg + lane; i < end; i += 32) {
        int s = g_src_sorted[i];
        float4 al = ((const float4*)g_als1)[s];
        float4 ex4;
        ex4.x = __expf(lrelu(al.x + ald[0]) - mx[0]);
        ex4.y = __expf(lrelu(al.y + ald[1]) - mx[1]);
        ex4.z = __expf(lrelu(al.z + ald[2]) - mx[2]);
        ex4.w = __expf(lrelu(al.w + ald[3]) - mx[3]);
        sm[0] += ex4.x; sm[1] += ex4.y; sm[2] += ex4.z; sm[3] += ex4.w;
        ((float4*)g_alpha1)[i] = ex4;
    }
#pragma unroll
    for (int h = 0; h < 4; h++) sm[h] = warpSum(sm[h]);
    float inv[4];
#pragma unroll
    for (int h = 0; h < 4; h++) inv[h] = 1.f / sm[h];
    __syncwarp();

    float acc[16];
#pragma unroll
    for (int j = 0; j < 16; j++) acc[j] = 0.f;
    int i = beg;
    for (; i + 3 < end; i += 4) {
        int s0 = g_src_sorted[i],     s1 = g_src_sorted[i + 1];
        int s2 = g_src_sorted[i + 2], s3 = g_src_sorted[i + 3];
        float4 a0 = ((const float4*)g_alpha1)[i];
        float4 a1 = ((const float4*)g_alpha1)[i + 1];
        float4 a2 = ((const float4*)g_alpha1)[i + 2];
        float4 a3 = ((const float4*)g_alpha1)[i + 3];
        const float4* r0 = (const float4*)(g_h1 + (size_t)s0 * D1);
        const float4* r1 = (const float4*)(g_h1 + (size_t)s1 * D1);
        const float4* r2 = (const float4*)(g_h1 + (size_t)s2 * D1);
        const float4* r3 = (const float4*)(g_h1 + (size_t)s3 * D1);
#pragma unroll
        for (int h = 0; h < 4; h++) {
            float aa0 = (h == 0) ? a0.x : (h == 1) ? a0.y : (h == 2) ? a0.z : a0.w;
            float aa1 = (h == 0) ? a1.x : (h == 1) ? a1.y : (h == 2) ? a1.z : a1.w;
            float aa2 = (h == 0) ? a2.x : (h == 1) ? a2.y : (h == 2) ? a2.z : a2.w;
            float aa3 = (h == 0) ? a3.x : (h == 1) ? a3.y : (h == 2) ? a3.z : a3.w;
            float4 v0 = r0[h * 32 + lane];
            float4 v1 = r1[h * 32 + lane];
            float4 v2 = r2[h * 32 + lane];
            float4 v3 = r3[h * 32 + lane];
            acc[h * 4 + 0] = fmaf(aa0, v0.x, fmaf(aa1, v1.x, fmaf(aa2, v2.x, fmaf(aa3, v3.x, acc[h * 4 + 0]))));
            acc[h * 4 + 1] = fmaf(aa0, v0.y, fmaf(aa1, v1.y, fmaf(aa2, v2.y, fmaf(aa3, v3.y, acc[h * 4 + 1]))));
            acc[h * 4 + 2] = fmaf(aa0, v0.z, fmaf(aa1, v1.z, fmaf(aa2, v2.z, fmaf(aa3, v3.z, acc[h * 4 + 2]))));
            acc[h * 4 + 3] = fmaf(aa0, v0.w, fmaf(aa1, v1.w, fmaf(aa2, v2.w, fmaf(aa3, v3.w, acc[h * 4 + 3]))));
        }
    }
    for (; i < end; i++) {
        int s0 = g_src_sorted[i];
        float4 a0 = ((const float4*)g_alpha1)[i];
        const float4* r0 = (const float4*)(g_h1 + (size_t)s0 * D1);
#pragma unroll
        for (int h = 0; h < 4; h++) {
            float aa0 = (h == 0) ? a0.x : (h == 1) ? a0.y : (h == 2) ? a0.z : a0.w;
            float4 v0 = r0[h * 32 + lane];
            acc[h * 4 + 0] = fmaf(aa0, v0.x, acc[h * 4 + 0]);
            acc[h * 4 + 1] = fmaf(aa0, v0.y, acc[h * 4 + 1]);
            acc[h * 4 + 2] = fmaf(aa0, v0.z, acc[h * 4 + 2]);
            acc[h * 4 + 3] = fmaf(aa0, v0.w, acc[h * 4 + 3]);
        }
    }
#pragma unroll
    for (int h = 0; h < 4; h++) {
        float4 bb = ((const float4*)b1)[h * 32 + lane];
        float v0 = fmaxf(acc[h * 4 + 0] * inv[h] + bb.x, 0.f);
        float v1 = fmaxf(acc[h * 4 + 1] * inv[h] + bb.y, 0.f);
        float v2 = fmaxf(acc[h * 4 + 2] * inv[h] + bb.z, 0.f);
        float v3 = fmaxf(acc[h * 4 + 3] * inv[h] + bb.w, 0.f);
        float h0 = __bfloat162float(__float2bfloat16(v0));
        float h1v = __bfloat162float(__float2bfloat16(v1));
        float h2v = __bfloat162float(__float2bfloat16(v2));
        float h3v = __bfloat162float(__float2bfloat16(v3));
        uint2 hiw = make_uint2(packbf2(v0, v1), packbf2(v2, v3));
        uint2 low = make_uint2(packbf2(v0 - h0, v1 - h1v), packbf2(v2 - h2v, v3 - h3v));
        size_t o = tidx(gw, h * 128 + 4 * lane, NCK2);
        *(uint2*)((char*)g_o1h + o) = hiw;
        *(uint2*)((char*)g_o1l + o) = low;
    }
}

// ---------------- GAT layer 2 + fused global mean pool -----------------------------
__global__ __launch_bounds__(256) void gat_agg2(const float* __restrict__ b2,
                                                const int* __restrict__ batch) {
    int gw = (blockIdx.x * blockDim.x + threadIdx.x) >> 5;
    int lane = threadIdx.x & 31;
    if (gw >= N_NODES) return;
    int beg = g_offsets[gw], end = g_offsets[gw + 1];
    float ald = g_ald2[gw];

    float mx = -1e30f;
    for (int i = beg + lane; i < end; i += 32)
        mx = fmaxf(mx, lrelu(g_als2[g_src_sorted[i]] + ald));
    mx = warpMax(mx);

    float sm = 0.f;
    for (int i = beg + lane; i < end; i += 32) {
        float e = lrelu(g_als2[g_src_sorted[i]] + ald);
        float ex = __expf(e - mx);
        g_alpha2[i] = ex;
        sm += ex;
    }
    sm = warpSum(sm);
    float inv = 1.f / sm;
    __syncwarp();

    float acc[4] = {0, 0, 0, 0};
    int i = beg;
    for (; i + 3 < end; i += 4) {
        int s0 = g_src_sorted[i],     s1 = g_src_sorted[i + 1];
        int s2 = g_src_sorted[i + 2], s3 = g_src_sorted[i + 3];
        float a0 = g_alpha2[i],     a1 = g_alpha2[i + 1];
        float a2 = g_alpha2[i + 2], a3 = g_alpha2[i + 3];
        float4 v0 = ((const float4*)(g_h2 + (size_t)s0 * HID))[lane];
        float4 v1 = ((const float4*)(g_h2 + (size_t)s1 * HID))[lane];
        float4 v2 = ((const float4*)(g_h2 + (size_t)s2 * HID))[lane];
        float4 v3 = ((const float4*)(g_h2 + (size_t)s3 * HID))[lane];
        acc[0] = fmaf(a0, v0.x, fmaf(a1, v1.x, fmaf(a2, v2.x, fmaf(a3, v3.x, acc[0]))));
        acc[1] = fmaf(a0, v0.y, fmaf(a1, v1.y, fmaf(a2, v2.y, fmaf(a3, v3.y, acc[1]))));
        acc[2] = fmaf(a0, v0.z, fmaf(a1, v1.z, fmaf(a2, v2.z, fmaf(a3, v3.z, acc[2]))));
        acc[3] = fmaf(a0, v0.w, fmaf(a1, v1.w, fmaf(a2, v2.w, fmaf(a3, v3.w, acc[3]))));
    }
    for (; i < end; i++) {
        int s0 = g_src_sorted[i];
        float a0 = g_alpha2[i];
        float4 v0 = ((const float4*)(g_h2 + (size_t)s0 * HID))[lane];
        acc[0] = fmaf(a0, v0.x, acc[0]);
        acc[1] = fmaf(a0, v0.y, acc[1]);
        acc[2] = fmaf(a0, v0.z, acc[2]);
        acc[3] = fmaf(a0, v0.w, acc[3]);
    }
    float4 bb = ((const float4*)b2)[lane];
    int g = batch[gw];
    float* pool = g_pool + g * HID + 4 * lane;
    atomicAdd(&pool[0], fmaxf(acc[0] * inv + bb.x, 0.f));
    atomicAdd(&pool[1], fmaxf(acc[1] * inv + bb.y, 0.f));
    atomicAdd(&pool[2], fmaxf(acc[2] * inv + bb.z, 0.f));
    atomicAdd(&pool[3], fmaxf(acc[3] * inv + bb.w, 0.f));
    if (lane == 0) atomicAdd(&g_cnt[g], 1);
}

// ---------------- MLP head ---------------------------------------------------------
__global__ __launch_bounds__(1024) void mlp_kernel(
    const float* __restrict__ fc1_w, const float* __restrict__ fc1_b,
    const float* __restrict__ fc2_w, const float* __restrict__ fc2_b,
    float* __restrict__ out)
{
    __shared__ float pooled[NUM_GRAPHS * HID];
    __shared__ float z[NUM_GRAPHS * 64];
    int tid = threadIdx.x;
    for (int i = tid; i < NUM_GRAPHS * HID; i += blockDim.x) {
        int g = i / HID;
        float c = fmaxf((float)g_cnt[g], 1.f);
        pooled[i] = g_pool[i] / c;
    }
    __syncthreads();
    for (int i = tid; i < NUM_GRAPHS * 64; i += blockDim.x) {
        int g = i >> 6, j = i & 63;
        float acc = fc1_b[j];
        for (int k = 0; k < HID; k++)
            acc = fmaf(pooled[g * HID + k], fc1_w[k * 64 + j], acc);
        z[i] = fmaxf(acc, 0.f);
    }
    __syncthreads();
    for (int i = tid; i < NUM_GRAPHS * NUM_CLASSES; i += blockDim.x) {
        int g = i / NUM_CLASSES, c = i % NUM_CLASSES;
        float acc = fc2_b[c];
        for (int j = 0; j < 64; j++)
            acc = fmaf(z[g * 64 + j], fc2_w[j * NUM_CLASSES + c], acc);
        out[i] = acc;
    }
}

// ---------------- launch -------------------------------------------------------------
extern "C" void kernel_launch(void* const* d_in, const int* in_sizes, int n_in,
                              void* d_out, int out_size) {
    const float* x       = (const float*)d_in[0];
    const int*   ei      = (const int*)  d_in[1];
    const int*   batch   = (const int*)  d_in[2];
    const float* W1      = (const float*)d_in[3];
    const float* a_src1  = (const float*)d_in[4];
    const float* a_dst1  = (const float*)d_in[5];
    const float* b1      = (const float*)d_in[6];
    const float* W2      = (const float*)d_in[7];
    const float* a_src2  = (const float*)d_in[8];
    const float* a_dst2  = (const float*)d_in[9];
    const float* b2      = (const float*)d_in[10];
    const float* fc1_w   = (const float*)d_in[11];
    const float* fc1_b   = (const float*)d_in[12];
    const float* fc2_w   = (const float*)d_in[13];
    const float* fc2_b   = (const float*)d_in[14];
    float* out = (float*)d_out;

    static float *p_h1, *p_h2, *p_als1, *p_ald1, *p_als2, *p_ald2;
    static __nv_bfloat16 *p_xh, *p_xl, *p_o1h, *p_o1l, *p_b1h, *p_b1l, *p_b2h, *p_b2l;
    static bool inited = false;
    if (!inited) {
        cudaGetSymbolAddress((void**)&p_h1,   g_h1);
        cudaGetSymbolAddress((void**)&p_h2,   g_h2);
        cudaGetSymbolAddress((void**)&p_als1, g_als1);
        cudaGetSymbolAddress((void**)&p_ald1, g_ald1);
        cudaGetSymbolAddress((void**)&p_als2, g_als2);
        cudaGetSymbolAddress((void**)&p_ald2, g_ald2);
        cudaGetSymbolAddress((void**)&p_xh,  g_xh);
        cudaGetSymbolAddress((void**)&p_xl,  g_xl);
        cudaGetSymbolAddress((void**)&p_o1h, g_o1h);
        cudaGetSymbolAddress((void**)&p_o1l, g_o1l);
        cudaGetSymbolAddress((void**)&p_b1h, g_b1h);
        cudaGetSymbolAddress((void**)&p_b1l, g_b1l);
        cudaGetSymbolAddress((void**)&p_b2h, g_b2h);
        cudaGetSymbolAddress((void**)&p_b2l, g_b2l);
        cudaFuncSetAttribute(gemm_tc<256>, cudaFuncAttributeMaxDynamicSharedMemorySize, 199680);
        cudaFuncSetAttribute(gemm_tc<128>, cudaFuncAttributeMaxDynamicSharedMemorySize, 133632);
        inited = true;
    }

    // conversions (GEMM1 deps only)
    cvt_w_kernel<<<(D1 * (KP1 / 8) + HID * (D1 / 8) + 255) / 256, 256>>>(W1, W2);
    cvt_x_kernel<<<(ROWS_PAD * (KP1 / 8) + 255) / 256, 256>>>(x);
    zero_kernel<<<(N_NODES + 255) / 256, 256>>>();

    // index 3: GEMM1 (profiled): h1 = x @ W1 + fused attention coefs
    {
        dim3 grid(D1 / 256, RB_CNT);
        gemm_tc<256><<<grid, 256, 199680>>>(p_xh, p_xl, p_b1h, p_b1l, p_h1, N_NODES, D1, KP1,
                                            a_src1, a_dst1, p_als1, p_ald1, HEADS1);
    }
    {
        dim3 grid(D1 / 128, RB_CNT);
        gemm_simt<<<grid, 256>>>(p_xh, p_xl, p_b1h, p_b1l, p_h1, N_NODES, D1, KP1);
        att_coef1<<<(N_NODES * 32 + 255) / 256, 256>>>(a_src1, a_dst1);  // no-op on TC path
    }

    // CSR build (needed before gat_agg1)
    hist_kernel<<<(E_TOT + 255) / 256, 256>>>(ei);
    scan1_kernel<<<SCAN_NB, 256>>>();
    scan2_kernel<<<1, 256>>>();
    scan3_kernel<<<SCAN_NB, 256>>>();
    scatter_kernel<<<(E_TOT + 255) / 256, 256>>>(ei);

    gat_agg1<<<(N_NODES * 32 + 255) / 256, 256>>>(b1);

    // GEMM2: h2 = out1 @ W2 + fused attention coefs
    {
        dim3 grid(HID / 128, RB_CNT);
        gemm_tc<128><<<grid, 256, 133632>>>(p_o1h, p_o1l, p_b2h, p_b2l, p_h2, N_NODES, HID, D1,
                                            a_src2, a_dst2, p_als2, p_ald2, 1);
        gemm_simt<<<grid, 256>>>(p_o1h, p_o1l, p_b2h, p_b2l, p_h2, N_NODES, HID, D1);
        att_coef2<<<(N_NODES * 32 + 255) / 256, 256>>>(a_src2, a_dst2);  // no-op on TC path
    }
    gat_agg2<<<(N_NODES * 32 + 255) / 256, 256>>>(b2, batch);

    mlp_kernel<<<1, 1024>>>(fc1_w, fc1_b, fc2_w, fc2_b, out);
}

// round 17
// speedup vs baseline: 1.0436x; 1.0436x over previous
#include <cuda_runtime.h>
#include <cuda_bf16.h>
#include <cstdint>
#include <math.h>

#define N_NODES 50000
#define ROWS_PAD 50048       /* 391*128 */
#define RB_CNT  391
#define N_EDGES 400000
#define E_TOT   450000
#define IN_CH   814
#define KP1     832          /* 13*64 */
#define NCK1    13
#define HID     128
#define HEADS1  4
#define D1      (HEADS1*HID) /* 512 */
#define NCK2    8
#define NUM_CLASSES 46
#define NUM_GRAPHS  64
#define NEG_SLOPE   0.2f
#define SCAN_NB  196

#if defined(__CUDA_ARCH_FEAT_SM103_ALL) || defined(__CUDA_ARCH_FEAT_SM100_ALL)
#define HAS_TC 1
#else
#define HAS_TC 0
#endif

// ---------------- scratch (tiled operands: 16KB SW128 tiles, chunk-contiguous) ----
__device__ float g_h1[N_NODES * D1];
__device__ float g_h2[N_NODES * HID];
__device__ float g_out2[N_NODES * HID];
__device__ __nv_bfloat16 g_xh[ROWS_PAD * KP1];
__device__ __nv_bfloat16 g_xl[ROWS_PAD * KP1];
__device__ __nv_bfloat16 g_o1h[ROWS_PAD * D1];
__device__ __nv_bfloat16 g_o1l[ROWS_PAD * D1];
__device__ __nv_bfloat16 g_b1h[D1 * KP1];
__device__ __nv_bfloat16 g_b1l[D1 * KP1];
__device__ __nv_bfloat16 g_b2h[HID * D1];
__device__ __nv_bfloat16 g_b2l[HID * D1];
__device__ float g_als1[N_NODES * HEADS1];
__device__ float g_ald1[N_NODES * HEADS1];
__device__ float g_als2[N_NODES];
__device__ float g_ald2[N_NODES];
__device__ int   g_counts[N_NODES];
__device__ int   g_offsets[N_NODES + 1];
__device__ int   g_cursor[N_NODES];
__device__ int   g_bsum[SCAN_NB];
__device__ int   g_src_sorted[E_TOT];
__device__ float g_alpha1[E_TOT * HEADS1];
__device__ float g_alpha2[E_TOT];
__device__ float g_pool[NUM_GRAPHS * HID];
__device__ int   g_cnt[NUM_GRAPHS];

// tiled byte-offset: tile = (row>>7)*nck + (k>>6); within: SW128 of (row&127)*128+(k&63)*2
__device__ __forceinline__ size_t tidx(int row, int k, int nck) {
    uint32_t byte = ((uint32_t)(row & 127)) * 128u + (uint32_t)(k & 63) * 2u;
    byte ^= (byte >> 3) & 0x70u;
    return ((size_t)((row >> 7) * nck + (k >> 6)) << 14) + byte;
}

// ---------------- PTX helpers ----------------------------------------------------
#if HAS_TC
__device__ __forceinline__ uint32_t smem_u32(const void* p) {
    uint32_t a;
    asm("{ .reg .u64 t; cvta.to.shared.u64 t, %1; cvt.u32.u64 %0, t; }" : "=r"(a) : "l"(p));
    return a;
}
__device__ __forceinline__ uint32_t elect_one() {
    uint32_t pred;
    asm volatile("{ .reg .pred p; elect.sync _|p, 0xFFFFFFFF; selp.b32 %0, 1, 0, p; }" : "=r"(pred));
    return pred;
}
#define MBAR_INIT(a, n)  asm volatile("mbarrier.init.shared.b64 [%0], %1;" :: "r"(a), "r"((uint32_t)(n)) : "memory")
#define MBAR_EXPECT(a, b) asm volatile("mbarrier.arrive.expect_tx.shared.b64 _, [%0], %1;" :: "r"(a), "r"((uint32_t)(b)) : "memory")
#define MBAR_WAIT(a, ph) do { \
    uint32_t _m = (a), _p = (ph), _d; \
    asm volatile("{ .reg .pred p; mbarrier.try_wait.parity.acquire.cta.shared::cta.b64 p, [%1], %2; selp.b32 %0,1,0,p; }" \
        : "=r"(_d) : "r"(_m), "r"(_p) : "memory"); \
    if (!_d) { \
        asm volatile("{ .reg .pred P1;\nWL_%=:\nmbarrier.try_wait.parity.acquire.cta.shared::cta.b64 P1, [%0], %1, 0x989680;\n@P1 bra.uni WD_%=;\nbra.uni WL_%=;\nWD_%=:\n}" \
            :: "r"(_m), "r"(_p) : "memory"); \
    } } while (0)
#define TC_ALLOC(sa, n)   asm volatile("tcgen05.alloc.cta_group::1.sync.aligned.shared::cta.b32 [%0], %1;" :: "r"(sa), "r"((uint32_t)(n)) : "memory")
#define TC_DEALLOC(t, n)  asm volatile("tcgen05.dealloc.cta_group::1.sync.aligned.b32 %0, %1;" :: "r"(t), "r"((uint32_t)(n)))
#define TC_RELINQ()       asm volatile("tcgen05.relinquish_alloc_permit.cta_group::1.sync.aligned;")
#define TC_COMMIT(a)      asm volatile("tcgen05.commit.cta_group::1.mbarrier::arrive::one.shared::cluster.b64 [%0];" :: "r"(a) : "memory")
#define TC_FENCE_AFTER()  asm volatile("tcgen05.fence::after_thread_sync;" ::: "memory")
#define TC_FENCE_BEFORE() asm volatile("tcgen05.fence::before_thread_sync;" ::: "memory")
#define TC_WAIT_LD()      asm volatile("tcgen05.wait::ld.sync.aligned;" ::: "memory")
#define BULK_CP(dst, src, sz, mbar) \
    asm volatile("cp.async.bulk.shared::cta.global.mbarrier::complete_tx::bytes [%0], [%1], %2, [%3];" \
                 :: "r"(dst), "l"(src), "r"((uint32_t)(sz)), "r"(mbar) : "memory")
#define PREF_L2(src, sz) \
    asm volatile("cp.async.bulk.prefetch.L2.global [%0], %1;" :: "l"(src), "r"((uint32_t)(sz)) : "memory")

__device__ __forceinline__ void mma_f16_ss(uint32_t d, uint64_t ad, uint64_t bd,
                                           uint32_t idesc, bool accum) {
    uint32_t en = accum ? 1u : 0u, z = 0u;
    asm volatile(
        "{ .reg .pred p; setp.ne.u32 p, %5, 0;\n\t"
        "tcgen05.mma.cta_group::1.kind::f16 [%0], %1, %2, %3, {%4,%4,%4,%4}, p; }"
        :: "r"(d), "l"(ad), "l"(bd), "r"(idesc), "r"(z), "r"(en) : "memory");
}
__device__ __forceinline__ void tmem_ld32(uint32_t* r, uint32_t addr) {
    asm volatile(
        "tcgen05.ld.sync.aligned.32x32b.x32.b32 "
        "{%0,%1,%2,%3,%4,%5,%6,%7,%8,%9,%10,%11,%12,%13,%14,%15,"
        "%16,%17,%18,%19,%20,%21,%22,%23,%24,%25,%26,%27,%28,%29,%30,%31}, [%32];"
        : "=r"(r[0]), "=r"(r[1]), "=r"(r[2]), "=r"(r[3]), "=r"(r[4]), "=r"(r[5]), "=r"(r[6]), "=r"(r[7]),
          "=r"(r[8]), "=r"(r[9]), "=r"(r[10]), "=r"(r[11]), "=r"(r[12]), "=r"(r[13]), "=r"(r[14]), "=r"(r[15]),
          "=r"(r[16]), "=r"(r[17]), "=r"(r[18]), "=r"(r[19]), "=r"(r[20]), "=r"(r[21]), "=r"(r[22]), "=r"(r[23]),
          "=r"(r[24]), "=r"(r[25]), "=r"(r[26]), "=r"(r[27]), "=r"(r[28]), "=r"(r[29]), "=r"(r[30]), "=r"(r[31])
        : "r"(addr));
}
#define DESC_SW128(addr) ((uint64_t(2) << 61) | (uint64_t(1) << 46) | (uint64_t(64) << 32) \
                          | (uint64_t(1) << 16) | ((uint64_t)((addr) >> 4) & 0x3FFF))
#endif // HAS_TC

// -------- tcgen05 bf16x3 GEMM, bulk tile loads + L2 prefetch, fused epilogue -------
// (round-12 configuration: depth-2 SMEM pipeline, prefetch 3 chunks ahead)
template <int NT>
__global__ void __launch_bounds__(256)
gemm_tc(const __nv_bfloat16* __restrict__ Ah, const __nv_bfloat16* __restrict__ Al,
        const __nv_bfloat16* __restrict__ Bh, const __nv_bfloat16* __restrict__ Bl,
        float* __restrict__ C, int M, int ldc, int kp,
        const float* __restrict__ asrc, const float* __restrict__ adst,
        float* __restrict__ als, float* __restrict__ ald, int nheads)
{
#if HAS_TC
    extern __shared__ char dsm[];
    uint32_t sb = smem_u32(dsm);
    uint32_t base = (sb + 1023) & ~1023u;
    const uint32_t TM_PTR = base;
    const uint32_t MMABAR = base + 8;
    const uint32_t LBAR0  = base + 16;
    const uint32_t LBAR1  = base + 24;
    const uint32_t T0 = base + 1024;
    constexpr uint32_t ATILE = 16384;
    constexpr uint32_t BTILE = NT * 128;
    constexpr uint32_t OFF_AL = ATILE;
    constexpr uint32_t OFF_BH = 2 * ATILE;
    constexpr uint32_t OFF_BL = 2 * ATILE + BTILE;
    constexpr uint32_t BUFSZ  = 2 * ATILE + 2 * BTILE;
    constexpr uint32_t LOADB  = BUFSZ;

    int tid = threadIdx.x, wid = tid >> 5, lane = tid & 31;
    int rb = blockIdx.y;
    int m0 = rb * 128, n0 = blockIdx.x * NT;
    int nb0 = n0 >> 7;
    const int nck = kp >> 6;

    if (wid == 0) { TC_ALLOC(TM_PTR, NT); TC_RELINQ(); }
    if (tid == 0) {
        MBAR_INIT(MMABAR, 1);
        MBAR_INIT(LBAR0, 1);
        MBAR_INIT(LBAR1, 1);
    }
    __syncthreads();
    uint32_t tmem;
    asm volatile("ld.shared.b32 %0, [%1];" : "=r"(tmem) : "r"(TM_PTR));

    const char* cAh = (const char*)Ah;
    const char* cAl = (const char*)Al;
    const char* cBh = (const char*)Bh;
    const char* cBl = (const char*)Bl;

    const uint32_t IDESC = 0x8000490u | ((NT / 8) << 17);

    auto issue = [&](int c, uint32_t buf, uint32_t lbar) {
        MBAR_EXPECT(lbar, LOADB);
        size_t aoff = ((size_t)(rb * nck + c)) << 14;
        BULK_CP(buf,          cAh + aoff, 16384, lbar);
        BULK_CP(buf + OFF_AL, cAl + aoff, 16384, lbar);
        size_t b0off = ((size_t)(nb0 * nck + c)) << 14;
        BULK_CP(buf + OFF_BH, cBh + b0off, 16384, lbar);
        BULK_CP(buf + OFF_BL, cBl + b0off, 16384, lbar);
        if (NT == 256) {
            size_t b1off = ((size_t)((nb0 + 1) * nck + c)) << 14;
            BULK_CP(buf + OFF_BH + 16384, cBh + b1off, 16384, lbar);
            BULK_CP(buf + OFF_BL + 16384, cBl + b1off, 16384, lbar);
        }
    };
    auto pref = [&](int c) {
        size_t aoff = ((size_t)(rb * nck + c)) << 14;
        PREF_L2(cAh + aoff, 16384);
        PREF_L2(cAl + aoff, 16384);
        size_t b0off = ((size_t)(nb0 * nck + c)) << 14;
        PREF_L2(cBh + b0off, 16384);
        PREF_L2(cBl + b0off, 16384);
        if (NT == 256) {
            size_t b1off = ((size_t)((nb0 + 1) * nck + c)) << 14;
            PREF_L2(cBh + b1off, 16384);
            PREF_L2(cBl + b1off, 16384);
        }
    };

    if (tid == 0) {
        issue(0, T0, LBAR0);
        if (1 < nck) pref(1);
        if (2 < nck) pref(2);
        if (3 < nck) pref(3);
    }

    for (int c = 0; c < nck; c++) {
        uint32_t buf = T0 + (c & 1) * BUFSZ;
        MBAR_WAIT((c & 1) ? LBAR1 : LBAR0, (c >> 1) & 1);
        if (wid == 0 && elect_one()) {
            uint64_t dAH = DESC_SW128(buf);
            uint64_t dAL = DESC_SW128(buf + OFF_AL);
            uint64_t dBH = DESC_SW128(buf + OFF_BH);
            uint64_t dBL = DESC_SW128(buf + OFF_BL);
#pragma unroll
            for (int k = 0; k < 4; k++) mma_f16_ss(tmem, dAH + 2 * k, dBH + 2 * k, IDESC, !(c == 0 && k == 0));
#pragma unroll
            for (int k = 0; k < 4; k++) mma_f16_ss(tmem, dAL + 2 * k, dBH + 2 * k, IDESC, true);
#pragma unroll
            for (int k = 0; k < 4; k++) mma_f16_ss(tmem, dAH + 2 * k, dBL + 2 * k, IDESC, true);
            TC_COMMIT(MMABAR);
        }
        if (tid == 0 && c + 1 < nck) {
            issue(c + 1, T0 + ((c + 1) & 1) * BUFSZ, ((c + 1) & 1) ? LBAR1 : LBAR0);
            if (c + 4 < nck) pref(c + 4);
        }
        MBAR_WAIT(MMABAR, c & 1);
    }

    TC_FENCE_AFTER();
    if (wid < 4) {
        int row = m0 + wid * 32 + lane;
#pragma unroll
        for (int hloc = 0; hloc < NT / 128; hloc++) {
            float s = 0.f, d = 0.f;
#pragma unroll
            for (int nb = 0; nb < 4; nb++) {
                int batch = hloc * 4 + nb;
                uint32_t rg[32];
                tmem_ld32(rg, tmem + batch * 32);
                TC_WAIT_LD();
                if (row < M) {
                    float4* dst = (float4*)(C + (size_t)row * ldc + n0 + batch * 32);
#pragma unroll
                    for (int i = 0; i < 8; i++)
                        dst[i] = make_float4(__uint_as_float(rg[4 * i]), __uint_as_float(rg[4 * i + 1]),
                                             __uint_as_float(rg[4 * i + 2]), __uint_as_float(rg[4 * i + 3]));
                }
#pragma unroll
                for (int i = 0; i < 32; i++) {
                    float v = __uint_as_float(rg[i]);
                    int col = n0 + batch * 32 + i;
                    s = fmaf(v, __ldg(&asrc[col]), s);
                    d = fmaf(v, __ldg(&adst[col]), d);
                }
            }
            if (row < M) {
                int head = n0 / 128 + hloc;
                als[(size_t)row * nheads + head] = s;
                ald[(size_t)row * nheads + head] = d;
            }
        }
        TC_FENCE_BEFORE();
    }
    __syncthreads();
    if (wid == 0) TC_DEALLOC(tmem, NT);
#endif
}

// ---------------- SIMT fallback (active only when !HAS_TC; reads tiled layout) -----
__global__ __launch_bounds__(256) void gemm_simt(
    const __nv_bfloat16* __restrict__ Ah, const __nv_bfloat16* __restrict__ Al,
    const __nv_bfloat16* __restrict__ Bh, const __nv_bfloat16* __restrict__ Bl,
    float* __restrict__ C, int M, int ldc, int kp)
{
#if !HAS_TC
    __shared__ float As[8][128];
    __shared__ float Bs[8][128];
    int tid = threadIdx.x;
    int tx = tid & 15, ty = tid >> 4;
    int rowBase = blockIdx.y * 128;
    int colBase = blockIdx.x * 128;
    int nck = kp >> 6;

    float acc[8][8];
#pragma unroll
    for (int i = 0; i < 8; i++)
#pragma unroll
        for (int j = 0; j < 8; j++) acc[i][j] = 0.f;

    for (int k0 = 0; k0 < kp; k0 += 8) {
#pragma unroll
        for (int i = 0; i < 4; i++) {
            int idx = tid + 256 * i;
            int rr = idx >> 3, cc = idx & 7;
            int gr = rowBase + rr;
            size_t o = tidx(gr, k0 + cc, nck);
            float v = __bfloat162float(*(const __nv_bfloat16*)((const char*)Ah + o))
                    + __bfloat162float(*(const __nv_bfloat16*)((const char*)Al + o));
            As[cc][rr] = v;
        }
#pragma unroll
        for (int i = 0; i < 4; i++) {
            int idx = tid + 256 * i;
            int nl = idx >> 3, kk = idx & 7;
            size_t o = tidx(colBase + nl, k0 + kk, nck);
            Bs[kk][nl] = __bfloat162float(*(const __nv_bfloat16*)((const char*)Bh + o))
                       + __bfloat162float(*(const __nv_bfloat16*)((const char*)Bl + o));
        }
        __syncthreads();
#pragma unroll
        for (int kk = 0; kk < 8; kk++) {
            float a[8], b[8];
#pragma unroll
            for (int i = 0; i < 8; i++) a[i] = As[kk][ty * 8 + i];
#pragma unroll
            for (int j = 0; j < 8; j++) b[j] = Bs[kk][tx * 8 + j];
#pragma unroll
            for (int i = 0; i < 8; i++)
#pragma unroll
                for (int j = 0; j < 8; j++) acc[i][j] = fmaf(a[i], b[j], acc[i][j]);
        }
        __syncthreads();
    }
#pragma unroll
    for (int i = 0; i < 8; i++) {
        int gr = rowBase + ty * 8 + i;
        if (gr >= M) continue;
#pragma unroll
        for (int j = 0; j < 8; j++)
            C[(size_t)gr * ldc + colBase + tx * 8 + j] = acc[i][j];
    }
#endif
}

// ---------------- misc helpers -----------------------------------------------
__device__ __forceinline__ float warpMax(float v) {
#pragma unroll
    for (int o = 16; o > 0; o >>= 1) v = fmaxf(v, __shfl_xor_sync(0xffffffffu, v, o));
    return v;
}
__device__ __forceinline__ float warpSum(float v) {
#pragma unroll
    for (int o = 16; o > 0; o >>= 1) v += __shfl_xor_sync(0xffffffffu, v, o);
    return v;
}
__device__ __forceinline__ float lrelu(float x) { return x > 0.f ? x : NEG_SLOPE * x; }
__device__ __forceinline__ uint32_t packbf2(float a, float b) {
    __nv_bfloat162 t;
    t.x = __float2bfloat16(a);
    t.y = __float2bfloat16(b);
    return *(uint32_t*)&t;
}

// ---------------- conversions (write tiled+swizzled) ---------------------------
__global__ void cvt_w_kernel(const float* __restrict__ W1, const float* __restrict__ W2) {
    int idx = blockIdx.x * blockDim.x + threadIdx.x;
    const int n1 = D1 * KP1;
    if (idx < n1) {
        int n = idx / KP1, k = idx - n * KP1;
        float v = (k < IN_CH) ? W1[(size_t)k * D1 + n] : 0.f;
        __nv_bfloat16 hi = __float2bfloat16(v);
        size_t o = tidx(n, k, NCK1);
        *(__nv_bfloat16*)((char*)g_b1h + o) = hi;
        *(__nv_bfloat16*)((char*)g_b1l + o) = __float2bfloat16(v - __bfloat162float(hi));
        return;
    }
    int j = idx - n1;
    if (j < HID * D1) {
        int n = j / D1, k = j - n * D1;
        float v = W2[(size_t)k * HID + n];
        __nv_bfloat16 hi = __float2bfloat16(v);
        size_t o = tidx(n, k, NCK2);
        *(__nv_bfloat16*)((char*)g_b2h + o) = hi;
        *(__nv_bfloat16*)((char*)g_b2l + o) = __float2bfloat16(v - __bfloat162float(hi));
    }
}

__global__ void cvt_x_kernel(const float* __restrict__ x) {
    int idx = blockIdx.x * blockDim.x + threadIdx.x;
    if (idx >= ROWS_PAD * KP1) return;
    int row = idx / KP1, k = idx - row * KP1;
    float v = (row < N_NODES && k < IN_CH) ? x[(size_t)row * IN_CH + k] : 0.f;
    __nv_bfloat16 hi = __float2bfloat16(v);
    size_t o = tidx(row, k, NCK1);
    *(__nv_bfloat16*)((char*)g_xh + o) = hi;
    *(__nv_bfloat16*)((char*)g_xl + o) = __float2bfloat16(v - __bfloat162float(hi));
}

__global__ void zero_kernel() {
    int i = blockIdx.x * blockDim.x + threadIdx.x;
    if (i < N_NODES) g_counts[i] = 0;
    if (i < NUM_GRAPHS * HID) g_pool[i] = 0.f;
    if (i < NUM_GRAPHS) g_cnt[i] = 0;
}

__global__ void hist_kernel(const int* __restrict__ ei) {
    int e = blockIdx.x * blockDim.x + threadIdx.x;
    if (e >= E_TOT) return;
    int dst = (e < N_EDGES) ? ei[N_EDGES + e] : (e - N_EDGES);
    atomicAdd(&g_counts[dst], 1);
}

__global__ void scan1_kernel() {
    __shared__ int sh[256];
    int b = blockIdx.x, tid = threadIdx.x;
    int i = b * 256 + tid;
    int v = (i < N_NODES) ? g_counts[i] : 0;
    sh[tid] = v;
    __syncthreads();
#pragma unroll
    for (int o = 1; o < 256; o <<= 1) {
        int t = (tid >= o) ? sh[tid - o] : 0;
        __syncthreads();
        sh[tid] += t;
        __syncthreads();
    }
    if (i < N_NODES) g_offsets[i] = sh[tid] - v;
    if (tid == 255) g_bsum[b] = sh[255];
}

__global__ void scan2_kernel() {
    __shared__ int sh[SCAN_NB];
    int tid = threadIdx.x;
    int v = (tid < SCAN_NB) ? g_bsum[tid] : 0;
    if (tid < SCAN_NB) sh[tid] = v;
    __syncthreads();
    for (int o = 1; o < SCAN_NB; o <<= 1) {
        int t = (tid >= o && tid < SCAN_NB) ? sh[tid - o] : 0;
        __syncthreads();
        if (tid < SCAN_NB) sh[tid] += t;
        __syncthreads();
    }
    if (tid < SCAN_NB) g_bsum[tid] = sh[tid] - v;
    if (tid == 0) g_offsets[N_NODES] = E_TOT;
}

__global__ void scan3_kernel() {
    int b = blockIdx.x, tid = threadIdx.x;
    int i = b * 256 + tid;
    if (i >= N_NODES) return;
    int off = g_offsets[i] + g_bsum[b];
    g_offsets[i] = off;
    g_cursor[i] = off;
}

__global__ void scatter_kernel(const int* __restrict__ ei) {
    int e = blockIdx.x * blockDim.x + threadIdx.x;
    if (e >= E_TOT) return;
    int src, dst;
    if (e < N_EDGES) { src = ei[e]; dst = ei[N_EDGES + e]; }
    else             { src = e - N_EDGES; dst = src; }
    int pos = atomicAdd(&g_cursor[dst], 1);
    g_src_sorted[pos] = src;
}

// ---------------- attention coefficients (fallback only) ---------------------------
__global__ void att_coef1(const float* __restrict__ a_src, const float* __restrict__ a_dst) {
#if !HAS_TC
    int gw = (blockIdx.x * blockDim.x + threadIdx.x) >> 5;
    int lane = threadIdx.x & 31;
    if (gw >= N_NODES) return;
    const float* row = g_h1 + (size_t)gw * D1;
    float s[4] = {0, 0, 0, 0}, d[4] = {0, 0, 0, 0};
#pragma unroll
    for (int j = 0; j < 16; j++) {
        int c = lane + 32 * j;
        float v = row[c];
        s[j >> 2] = fmaf(v, a_src[c], s[j >> 2]);
        d[j >> 2] = fmaf(v, a_dst[c], d[j >> 2]);
    }
#pragma unroll
    for (int h = 0; h < 4; h++) { s[h] = warpSum(s[h]); d[h] = warpSum(d[h]); }
    if (lane == 0) {
#pragma unroll
        for (int h = 0; h < 4; h++) {
            g_als1[gw * 4 + h] = s[h];
            g_ald1[gw * 4 + h] = d[h];
        }
    }
#endif
}

__global__ void att_coef2(const float* __restrict__ a_src, const float* __restrict__ a_dst) {
#if !HAS_TC
    int gw = (blockIdx.x * blockDim.x + threadIdx.x) >> 5;
    int lane = threadIdx.x & 31;
    if (gw >= N_NODES) return;
    const float* row = g_h2 + (size_t)gw * HID;
    float s = 0.f, d = 0.f;
#pragma unroll
    for (int j = 0; j < 4; j++) {
        int c = lane + 32 * j;
        float v = row[c];
        s = fmaf(v, a_src[c], s);
        d = fmaf(v, a_dst[c], d);
    }
    s = warpSum(s); d = warpSum(d);
    if (lane == 0) { g_als2[gw] = s; g_ald2[gw] = d; }
#endif
}

// ---------------- GAT layer 1 softmax + aggregate (warp per dst node) ------------
// lane handles 4 contiguous cols per head: col = h*128 + 4*lane + i (float4 loads)
__global__ __launch_bounds__(256) void gat_agg1(const float* __restrict__ b1) {
    int gw = (blockIdx.x * blockDim.x + threadIdx.x) >> 5;
    int lane = threadIdx.x & 31;
    if (gw >= N_NODES) return;
    int beg = g_offsets[gw], end = g_offsets[gw + 1];

    float ald[4];
#pragma unroll
    for (int h = 0; h < 4; h++) ald[h] = g_ald1[gw * 4 + h];

    float mx[4] = {-1e30f, -1e30f, -1e30f, -1e30f};
    for (int i = beg + lane; i < end; i += 32) {
        int s = g_src_sorted[i];
        float4 al = ((const float4*)g_als1)[s];
        mx[0] = fmaxf(mx[0], lrelu(al.x + ald[0]));
        mx[1] = fmaxf(mx[1], lrelu(al.y + ald[1]));
        mx[2] = fmaxf(mx[2], lrelu(al.z + ald[2]));
        mx[3] = fmaxf(mx[3], lrelu(al.w + ald[3]));
    }
#pragma unroll
    for (int h = 0; h < 4; h++) mx[h] = warpMax(mx[h]);

    float sm[4] = {0, 0, 0, 0};
    for (int i = beg + lane; i < end; i += 32) {
        int s = g_src_sorted[i];
        float4 al = ((const float4*)g_als1)[s];
        float4 ex4;
        ex4.x = __expf(lrelu(al.x + ald[0]) - mx[0]);
        ex4.y = __expf(lrelu(al.y + ald[1]) - mx[1]);
        ex4.z = __expf(lrelu(al.z + ald[2]) - mx[2]);
        ex4.w = __expf(lrelu(al.w + ald[3]) - mx[3]);
        sm[0] += ex4.x; sm[1] += ex4.y; sm[2] += ex4.z; sm[3] += ex4.w;
        ((float4*)g_alpha1)[i] = ex4;
    }
#pragma unroll
    for (int h = 0; h < 4; h++) sm[h] = warpSum(sm[h]);
    float inv[4];
#pragma unroll
    for (int h = 0; h < 4; h++) inv[h] = 1.f / sm[h];
    __syncwarp();

    // aggregation: 4 float4 loads per edge (cols h*128 + 4*lane .. +3)
    float acc[16];
#pragma unroll
    for (int j = 0; j < 16; j++) acc[j] = 0.f;
    int i = beg;
    for (; i + 1 < end; i += 2) {
        int s0 = g_src_sorted[i], s1 = g_src_sorted[i + 1];
        float4 a0 = ((const float4*)g_alpha1)[i];
        float4 a1 = ((const float4*)g_alpha1)[i + 1];
        const float4* r0 = (const float4*)(g_h1 + (size_t)s0 * D1);
        const float4* r1 = (const float4*)(g_h1 + (size_t)s1 * D1);
#pragma unroll
        for (int h = 0; h < 4; h++) {
            float aa0 = (h == 0) ? a0.x : (h == 1) ? a0.y : (h == 2) ? a0.z : a0.w;
            float aa1 = (h == 0) ? a1.x : (h == 1) ? a1.y : (h == 2) ? a1.z : a1.w;
            float4 v0 = r0[h * 32 + lane];
            float4 v1 = r1[h * 32 + lane];
            acc[h * 4 + 0] = fmaf(aa0, v0.x, fmaf(aa1, v1.x, acc[h * 4 + 0]));
            acc[h * 4 + 1] = fmaf(aa0, v0.y, fmaf(aa1, v1.y, acc[h * 4 + 1]));
            acc[h * 4 + 2] = fmaf(aa0, v0.z, fmaf(aa1, v1.z, acc[h * 4 + 2]));
            acc[h * 4 + 3] = fmaf(aa0, v0.w, fmaf(aa1, v1.w, acc[h * 4 + 3]));
        }
    }
    if (i < end) {
        int s0 = g_src_sorted[i];
        float4 a0 = ((const float4*)g_alpha1)[i];
        const float4* r0 = (const float4*)(g_h1 + (size_t)s0 * D1);
#pragma unroll
        for (int h = 0; h < 4; h++) {
            float aa0 = (h == 0) ? a0.x : (h == 1) ? a0.y : (h == 2) ? a0.z : a0.w;
            float4 v0 = r0[h * 32 + lane];
            acc[h * 4 + 0] = fmaf(aa0, v0.x, acc[h * 4 + 0]);
            acc[h * 4 + 1] = fmaf(aa0, v0.y, acc[h * 4 + 1]);
            acc[h * 4 + 2] = fmaf(aa0, v0.z, acc[h * 4 + 2]);
            acc[h * 4 + 3] = fmaf(aa0, v0.w, acc[h * 4 + 3]);
        }
    }
    // epilogue: relu + bf16 hi/lo split into tiled layout (8B packed stores)
#pragma unroll
    for (int h = 0; h < 4; h++) {
        float4 bb = ((const float4*)b1)[h * 32 + lane];
        float v0 = fmaxf(acc[h * 4 + 0] * inv[h] + bb.x, 0.f);
        float v1 = fmaxf(acc[h * 4 + 1] * inv[h] + bb.y, 0.f);
        float v2 = fmaxf(acc[h * 4 + 2] * inv[h] + bb.z, 0.f);
        float v3 = fmaxf(acc[h * 4 + 3] * inv[h] + bb.w, 0.f);
        float h0 = __bfloat162float(__float2bfloat16(v0));
        float h1v = __bfloat162float(__float2bfloat16(v1));
        float h2v = __bfloat162float(__float2bfloat16(v2));
        float h3v = __bfloat162float(__float2bfloat16(v3));
        uint2 hiw = make_uint2(packbf2(v0, v1), packbf2(v2, v3));
        uint2 low = make_uint2(packbf2(v0 - h0, v1 - h1v), packbf2(v2 - h2v, v3 - h3v));
        size_t o = tidx(gw, h * 128 + 4 * lane, NCK2);
        *(uint2*)((char*)g_o1h + o) = hiw;
        *(uint2*)((char*)g_o1l + o) = low;
    }
}

// ---------------- GAT layer 2 (lane handles 4 contiguous cols) --------------------
__global__ __launch_bounds__(256) void gat_agg2(const float* __restrict__ b2) {
    int gw = (blockIdx.x * blockDim.x + threadIdx.x) >> 5;
    int lane = threadIdx.x & 31;
    if (gw >= N_NODES) return;
    int beg = g_offsets[gw], end = g_offsets[gw + 1];
    float ald = g_ald2[gw];

    float mx = -1e30f;
    for (int i = beg + lane; i < end; i += 32)
        mx = fmaxf(mx, lrelu(g_als2[g_src_sorted[i]] + ald));
    mx = warpMax(mx);

    float sm = 0.f;
    for (int i = beg + lane; i < end; i += 32) {
        float e = lrelu(g_als2[g_src_sorted[i]] + ald);
        float ex = __expf(e - mx);
        g_alpha2[i] = ex;
        sm += ex;
    }
    sm = warpSum(sm);
    float inv = 1.f / sm;
    __syncwarp();

    float acc[4] = {0, 0, 0, 0};
    int i = beg;
    for (; i + 1 < end; i += 2) {
        int s0 = g_src_sorted[i], s1 = g_src_sorted[i + 1];
        float a0 = g_alpha2[i], a1 = g_alpha2[i + 1];
        float4 v0 = ((const float4*)(g_h2 + (size_t)s0 * HID))[lane];
        float4 v1 = ((const float4*)(g_h2 + (size_t)s1 * HID))[lane];
        acc[0] = fmaf(a0, v0.x, fmaf(a1, v1.x, acc[0]));
        acc[1] = fmaf(a0, v0.y, fmaf(a1, v1.y, acc[1]));
        acc[2] = fmaf(a0, v0.z, fmaf(a1, v1.z, acc[2]));
        acc[3] = fmaf(a0, v0.w, fmaf(a1, v1.w, acc[3]));
    }
    if (i < end) {
        int s0 = g_src_sorted[i];
        float a0 = g_alpha2[i];
        float4 v0 = ((const float4*)(g_h2 + (size_t)s0 * HID))[lane];
        acc[0] = fmaf(a0, v0.x, acc[0]);
        acc[1] = fmaf(a0, v0.y, acc[1]);
        acc[2] = fmaf(a0, v0.z, acc[2]);
        acc[3] = fmaf(a0, v0.w, acc[3]);
    }
    float4 bb = ((const float4*)b2)[lane];
    float4 outv;
    outv.x = fmaxf(acc[0] * inv + bb.x, 0.f);
    outv.y = fmaxf(acc[1] * inv + bb.y, 0.f);
    outv.z = fmaxf(acc[2] * inv + bb.z, 0.f);
    outv.w = fmaxf(acc[3] * inv + bb.w, 0.f);
    ((float4*)(g_out2 + (size_t)gw * HID))[lane] = outv;
}

// ---------------- global mean pool -----------------------------------------------
__global__ void pool_kernel(const int* __restrict__ batch) {
    int gw = (blockIdx.x * blockDim.x + threadIdx.x) >> 5;
    int lane = threadIdx.x & 31;
    if (gw >= N_NODES) return;
    int g = batch[gw];
#pragma unroll
    for (int j = 0; j < 4; j++) {
        int c = lane + 32 * j;
        atomicAdd(&g_pool[g * HID + c], g_out2[(size_t)gw * HID + c]);
    }
    if (lane == 0) atomicAdd(&g_cnt[g], 1);
}

// ---------------- MLP head ---------------------------------------------------------
__global__ __launch_bounds__(1024) void mlp_kernel(
    const float* __restrict__ fc1_w, const float* __restrict__ fc1_b,
    const float* __restrict__ fc2_w, const float* __restrict__ fc2_b,
    float* __restrict__ out)
{
    __shared__ float pooled[NUM_GRAPHS * HID];
    __shared__ float z[NUM_GRAPHS * 64];
    int tid = threadIdx.x;
    for (int i = tid; i < NUM_GRAPHS * HID; i += blockDim.x) {
        int g = i / HID;
        float c = fmaxf((float)g_cnt[g], 1.f);
        pooled[i] = g_pool[i] / c;
    }
    __syncthreads();
    for (int i = tid; i < NUM_GRAPHS * 64; i += blockDim.x) {
        int g = i >> 6, j = i & 63;
        float acc = fc1_b[j];
        for (int k = 0; k < HID; k++)
            acc = fmaf(pooled[g * HID + k], fc1_w[k * 64 + j], acc);
        z[i] = fmaxf(acc, 0.f);
    }
    __syncthreads();
    for (int i = tid; i < NUM_GRAPHS * NUM_CLASSES; i += blockDim.x) {
        int g = i / NUM_CLASSES, c = i % NUM_CLASSES;
        float acc = fc2_b[c];
        for (int j = 0; j < 64; j++)
            acc = fmaf(z[g * 64 + j], fc2_w[j * NUM_CLASSES + c], acc);
        out[i] = acc;
    }
}

// ---------------- launch -------------------------------------------------------------
extern "C" void kernel_launch(void* const* d_in, const int* in_sizes, int n_in,
                              void* d_out, int out_size) {
    const float* x       = (const float*)d_in[0];
    const int*   ei      = (const int*)  d_in[1];
    const int*   batch   = (const int*)  d_in[2];
    const float* W1      = (const float*)d_in[3];
    const float* a_src1  = (const float*)d_in[4];
    const float* a_dst1  = (const float*)d_in[5];
    const float* b1      = (const float*)d_in[6];
    const float* W2      = (const float*)d_in[7];
    const float* a_src2  = (const float*)d_in[8];
    const float* a_dst2  = (const float*)d_in[9];
    const float* b2      = (const float*)d_in[10];
    const float* fc1_w   = (const float*)d_in[11];
    const float* fc1_b   = (const float*)d_in[12];
    const float* fc2_w   = (const float*)d_in[13];
    const float* fc2_b   = (const float*)d_in[14];
    float* out = (float*)d_out;

    static float *p_h1, *p_h2, *p_als1, *p_ald1, *p_als2, *p_ald2;
    static __nv_bfloat16 *p_xh, *p_xl, *p_o1h, *p_o1l, *p_b1h, *p_b1l, *p_b2h, *p_b2l;
    static bool tc_active = false;
    static bool inited = false;
    if (!inited) {
        cudaGetSymbolAddress((void**)&p_h1,   g_h1);
        cudaGetSymbolAddress((void**)&p_h2,   g_h2);
        cudaGetSymbolAddress((void**)&p_als1, g_als1);
        cudaGetSymbolAddress((void**)&p_ald1, g_ald1);
        cudaGetSymbolAddress((void**)&p_als2, g_als2);
        cudaGetSymbolAddress((void**)&p_ald2, g_ald2);
        cudaGetSymbolAddress((void**)&p_xh,  g_xh);
        cudaGetSymbolAddress((void**)&p_xl,  g_xl);
        cudaGetSymbolAddress((void**)&p_o1h, g_o1h);
        cudaGetSymbolAddress((void**)&p_o1l, g_o1l);
        cudaGetSymbolAddress((void**)&p_b1h, g_b1h);
        cudaGetSymbolAddress((void**)&p_b1l, g_b1l);
        cudaGetSymbolAddress((void**)&p_b2h, g_b2h);
        cudaGetSymbolAddress((void**)&p_b2l, g_b2l);
        cudaFuncSetAttribute(gemm_tc<256>, cudaFuncAttributeMaxDynamicSharedMemorySize, 199680);
        cudaFuncSetAttribute(gemm_tc<128>, cudaFuncAttributeMaxDynamicSharedMemorySize, 133632);
        // detect which compile path is live: tcgen05 body uses ~78+ regs, stub <16
        cudaFuncAttributes fa;
        if (cudaFuncGetAttributes(&fa, gemm_tc<256>) == cudaSuccess)
            tc_active = (fa.numRegs > 32);
        inited = true;
    }

    // conversions (GEMM1 deps only)
    cvt_w_kernel<<<(D1 * KP1 + HID * D1 + 255) / 256, 256>>>(W1, W2);
    cvt_x_kernel<<<(ROWS_PAD * KP1 + 255) / 256, 256>>>(x);
    zero_kernel<<<(N_NODES + 255) / 256, 256>>>();

    // GEMM1: h1 = x @ W1 + fused attention coefs
    {
        dim3 grid(D1 / 256, RB_CNT);
        gemm_tc<256><<<grid, 256, 199680>>>(p_xh, p_xl, p_b1h, p_b1l, p_h1, N_NODES, D1, KP1,
                                            a_src1, a_dst1, p_als1, p_ald1, HEADS1);
    }
    if (!tc_active) {
        dim3 grid(D1 / 128, RB_CNT);
        gemm_simt<<<grid, 256>>>(p_xh, p_xl, p_b1h, p_b1l, p_h1, N_NODES, D1, KP1);
        att_coef1<<<(N_NODES * 32 + 255) / 256, 256>>>(a_src1, a_dst1);
    }

    // CSR build (needed before gat_agg1)
    hist_kernel<<<(E_TOT + 255) / 256, 256>>>(ei);
    scan1_kernel<<<SCAN_NB, 256>>>();
    scan2_kernel<<<1, 256>>>();
    scan3_kernel<<<SCAN_NB, 256>>>();
    scatter_kernel<<<(E_TOT + 255) / 256, 256>>>(ei);

    gat_agg1<<<(N_NODES * 32 + 255) / 256, 256>>>(b1);

    // GEMM2: h2 = out1 @ W2 + fused attention coefs
    {
        dim3 grid(HID / 128, RB_CNT);
        gemm_tc<128><<<grid, 256, 133632>>>(p_o1h, p_o1l, p_b2h, p_b2l, p_h2, N_NODES, HID, D1,
                                            a_src2, a_dst2, p_als2, p_ald2, 1);
    }
    if (!tc_active) {
        dim3 grid(HID / 128, RB_CNT);
        gemm_simt<<<grid, 256>>>(p_o1h, p_o1l, p_b2h, p_b2l, p_h2, N_NODES, HID, D1);
        att_coef2<<<(N_NODES * 32 + 255) / 256, 256>>>(a_src2, a_dst2);
    }
    gat_agg2<<<(N_NODES * 32 + 255) / 256, 256>>>(b2);

    pool_kernel<<<(N_NODES * 32 + 255) / 256, 256>>>(batch);
    mlp_kernel<<<1, 1024>>>(fc1_w, fc1_b, fc2_w, fc2_b, out);
}